// round 12
// baseline (speedup 1.0000x reference)
#include <cuda_runtime.h>

// ---------------------------------------------------------------------------
// MultiLevelClassifier — routed experts, round 8.
//
// R7 post-mortem: all three load strategies converged to l3 ~180us because
// the per-chunk 8-stage wait->sync->compute chain keeps only ONE 16KB stage
// in flight. This round: block = (expert, 32-feature segment); its 32KB
// weight tile is fired as ONE cp.async burst (8 copies/thread, one commit,
// one wait) -> whole tile in flight, no stage chain. Block then serves ALL
// row-chunks of its expert from smem (l2 weight DRAM traffic /8).
// Split-K depth 32; fused last-block finish with self-resetting tickets
// (logic unchanged from passing R5-R7 kernels).
// ---------------------------------------------------------------------------

#define BB   1024
#define FF   1024
#define EE   256
#define L1C  16
#define L2C  8
#define L3C  32
#define NE3  128
#define FSEG 32
#define FS   (FF / FSEG)     // 32 features per seg-block

// scratch (device globals — no allocation allowed; zero-initialized)
__device__ int   g_cnt2[L1C];
__device__ int   g_cnt3[NE3];
__device__ int   g_rows2[L1C * BB];
__device__ int   g_rows3[NE3 * BB];
__device__ float g_part[FSEG * BB * EE];   // 33.5 MB split-K partials
__device__ int   g_tick1[64];              // 1  expert  x 64 chunks (R=16)
__device__ int   g_tick2[L1C * 64];        // 16 experts x 64 chunks (R=16)
__device__ int   g_tick3[NE3 * 128];       // 128 experts x 128 chunks (R=8)

// ---- packed f32x2 helpers --------------------------------------------------
__device__ __forceinline__ unsigned long long pack2f(float a, float b) {
    unsigned long long r;
    asm("mov.b64 %0, {%1, %2};" : "=l"(r) : "f"(a), "f"(b));
    return r;
}
__device__ __forceinline__ void fma_f32x2(unsigned long long& d,
                                          unsigned long long a,
                                          unsigned long long b) {
    asm("fma.rn.f32x2 %0, %1, %2, %0;" : "+l"(d) : "l"(a), "l"(b));
}
__device__ __forceinline__ float2 unpack2(unsigned long long v) {
    float2 r;
    asm("mov.b64 {%0, %1}, %2;" : "=f"(r.x), "=f"(r.y) : "l"(v));
    return r;
}

// ---- cp.async helpers ------------------------------------------------------
__device__ __forceinline__ void cp_async16(void* sdst, const void* gsrc) {
    unsigned sa = (unsigned)__cvta_generic_to_shared(sdst);
    asm volatile("cp.async.cg.shared.global [%0], [%1], 16;\n"
                 :: "r"(sa), "l"(gsrc));
}
__device__ __forceinline__ void cp_commit() {
    asm volatile("cp.async.commit_group;\n");
}
template <int N>
__device__ __forceinline__ void cp_wait() {
    asm volatile("cp.async.wait_group %0;\n" :: "n"(N));
}

// dynamic smem sizing (must match host launch config)
__host__ __device__ constexpr int smem_bytes(int RT) {
    int R = 4 * RT;
    return FS * EE * 4            // weight tile (32 KB)
         + R * FS * 4             // features
         + R * EE * 4             // fin: act
         + R * 8 * 4 * 2          // fin: reds/redq
         + R * 4 * 2              // fin: mean/rstd
         + R * 32 * 4;            // fin: lg
}

// ---------------------------------------------------------------------------
__global__ void k_init() {
    int t = threadIdx.x;
    if (t < L1C) g_cnt2[t] = 0;
    if (t < NE3) g_cnt3[t] = 0;
}

// ---------------------------------------------------------------------------
// Fused level kernel. Block (slot, seg(32), expert), 256 threads.
//   cg = tid&63 -> cols 4cg..4cg+3 ; rg = tid>>6 -> rows rg*RT.. (R=4*RT)
// Weight tile (32 f x 256 cols = 32 KB) loaded ONCE per block in a single
// cp.async burst; block loops over its expert's row chunks from smem.
// Finish (split-K reduce, LN, ReLU, W2, argmax, scatter) in last seg-block.
// ---------------------------------------------------------------------------
template <int RT, int L, bool MIX, bool DENSE>
__global__ __launch_bounds__(256) void k_level(
    const float* __restrict__ fx, const float* __restrict__ fy,
    const float* __restrict__ W1base,            // [NEXP][FF][EE]
    const float* __restrict__ gbase, const float* __restrict__ bbase,
    const float* __restrict__ W2base, const float* __restrict__ b2base,
    const int* __restrict__ rowlists, const int* __restrict__ cnts,
    float* __restrict__ logits_out,
    int* __restrict__ cnt_next, int* __restrict__ rows_next,
    int* __restrict__ ticks)
{
    constexpr int R    = 4 * RT;
    constexpr int CMAX = BB / R;
    const int tid  = threadIdx.x;
    const int cg   = tid & 63;
    const int rg   = tid >> 6;
    const int slot = blockIdx.x, nslot = gridDim.x;
    const int seg  = blockIdx.y;
    const int e    = blockIdx.z;
    const int f0   = seg * FS;
    const int cnt  = DENSE ? BB : cnts[e];
    if (slot * R >= cnt) return;               // no chunk for this slot

    const float* __restrict__ Wseg =
        W1base + (size_t)e * FF * EE + (size_t)f0 * EE;   // 32 KB slice
    const float* __restrict__ gg = gbase  + (size_t)e * EE;
    const float* __restrict__ bv = bbase  + (size_t)e * EE;
    const float* __restrict__ W2 = W2base + (size_t)e * EE * L;
    const float* __restrict__ b2 = b2base + (size_t)e * L;

    extern __shared__ char smraw[];
    float* wbuf = (float*)smraw;                         // [FS][EE]
    float* feat = wbuf + FS * EE;                        // [R][FS]
    float* act  = feat + R * FS;                         // [R][EE]
    float* reds = act  + R * EE;                         // [R][8]
    float* redq = reds + R * 8;                          // [R][8]
    float* mean = redq + R * 8;                          // [R]
    float* rstd = mean + R;                              // [R]
    float* lg   = rstd + R;                              // [R][32]
    __shared__ int sflag;

    // ---- ONE weight burst: 8 cp.async per thread, single group ----------
    #pragma unroll
    for (int k = 0; k < 8; k++)
        cp_async16(wbuf + k * 1024 + tid * 4, Wseg + k * 1024 + tid * 4);
    cp_commit();

    bool wready = false;
    for (int c = slot; c * R < cnt; c += nslot) {
        const int start = c * R;
        const int nr = min(R, cnt - start);
        const int* rowids = DENSE ? nullptr : (rowlists + e * BB + start);

        // ---- feature chunk load (R rows x 32 f) -------------------------
        for (int i = tid; i < R * FS / 4; i += 256) {
            int r  = i / (FS / 4);
            int j  = (i % (FS / 4)) * 4;
            int rr = (r < nr) ? r : 0;
            int b  = DENSE ? (start + rr) : rowids[rr];
            float4 v = *(const float4*)(fx + (size_t)b * FF + f0 + j);
            if (MIX) {
                float4 u = *(const float4*)(fy + (size_t)b * FF + f0 + j);
                v.x = 0.6f * v.x + 0.4f * u.x;
                v.y = 0.6f * v.y + 0.4f * u.y;
                v.z = 0.6f * v.z + 0.4f * u.z;
                v.w = 0.6f * v.w + 0.4f * u.w;
            }
            *(float4*)&feat[r * FS + j] = v;
        }
        if (!wready) { cp_wait<0>(); wready = true; }
        __syncthreads();

        // ---- GEMM from smem: RT rows x 4 cols per thread ----------------
        unsigned long long acc[RT][2];
        #pragma unroll
        for (int t = 0; t < RT; t++) { acc[t][0] = 0ull; acc[t][1] = 0ull; }

        #pragma unroll
        for (int f = 0; f < FS; f++) {
            ulonglong2 w = *(const ulonglong2*)&wbuf[f * EE + 4 * cg];
            #pragma unroll
            for (int t = 0; t < RT; t++) {
                float v = feat[(rg * RT + t) * FS + f];
                unsigned long long fv = pack2f(v, v);
                fma_f32x2(acc[t][0], fv, w.x);
                fma_f32x2(acc[t][1], fv, w.y);
            }
        }

        // ---- write partials (STG.128) -----------------------------------
        #pragma unroll
        for (int t = 0; t < RT; t++) {
            int r = rg * RT + t;
            if (r < nr) {
                int b = DENSE ? (start + r) : rowids[r];
                float2 lo = unpack2(acc[t][0]);
                float2 hi = unpack2(acc[t][1]);
                *(float4*)&g_part[((size_t)seg * BB + b) * EE + 4 * cg] =
                    make_float4(lo.x, lo.y, hi.x, hi.y);
            }
        }

        // ---- split-K completion ticket ----------------------------------
        __threadfence();
        __syncthreads();
        if (tid == 0) {
            int* tk = &ticks[e * CMAX + c];
            int old = atomicAdd(tk, 1);
            if (old == FSEG - 1) *tk = 0;          // self-reset for replays
            sflag = old;
        }
        __syncthreads();
        if (sflag != FSEG - 1) continue;

        // =================== FINISH (reducer block only) =================
        __threadfence();

        float h[R];
        #pragma unroll
        for (int r = 0; r < R; r++) {
            int rr = (r < nr) ? r : 0;
            int b  = DENSE ? (start + rr) : rowids[rr];
            float s = 0.f;
            #pragma unroll
            for (int sg = 0; sg < FSEG; sg++)
                s += g_part[((size_t)sg * BB + b) * EE + tid];
            h[r] = s;
        }

        const int lane = tid & 31, wid = tid >> 5;
        #pragma unroll
        for (int r = 0; r < R; r++) {
            float s = h[r], q = h[r] * h[r];
            #pragma unroll
            for (int o = 16; o; o >>= 1) {
                s += __shfl_xor_sync(0xffffffffu, s, o);
                q += __shfl_xor_sync(0xffffffffu, q, o);
            }
            if (lane == 0) { reds[r * 8 + wid] = s; redq[r * 8 + wid] = q; }
        }
        __syncthreads();
        if (tid < R) {
            float s = 0.f, q = 0.f;
            #pragma unroll
            for (int w2i = 0; w2i < 8; w2i++) {
                s += reds[tid * 8 + w2i]; q += redq[tid * 8 + w2i];
            }
            float m   = s * (1.0f / EE);
            float var = q * (1.0f / EE) - m * m;
            mean[tid] = m;
            rstd[tid] = rsqrtf(var + 1e-5f);
        }
        __syncthreads();

        const float gt = gg[tid], bt = bv[tid];
        #pragma unroll
        for (int r = 0; r < R; r++) {
            float yv = (h[r] - mean[r]) * rstd[r] * gt + bt;
            act[r * EE + tid] = fmaxf(yv, 0.0f);
        }
        __syncthreads();

        // second matmul: logits
        for (int i = tid; i < nr * L; i += 256) {
            int r = i / L, col = i % L;
            float a = b2[col];
            const float* ar = &act[r * EE];
            #pragma unroll 8
            for (int k = 0; k < EE; k++) a += ar[k] * W2[k * L + col];
            lg[r * 32 + col] = a;
            int b = DENSE ? (start + r) : rowids[r];
            logits_out[(size_t)b * L + col] = a;
        }
        __syncthreads();

        // argmax + scatter
        if (cnt_next && tid < nr) {
            float best = lg[tid * 32];
            int   bi   = 0;
            #pragma unroll
            for (int col = 1; col < L; col++) {
                float v = lg[tid * 32 + col];
                if (v > best) { best = v; bi = col; }
            }
            int b   = DENSE ? (start + tid) : rowids[tid];
            int nxt = e * L + bi;
            int pos = atomicAdd(&cnt_next[nxt], 1);
            rows_next[nxt * BB + pos] = b;
        }
        __syncthreads();
    }
}

// ---------------------------------------------------------------------------
extern "C" void kernel_launch(void* const* d_in, const int* in_sizes, int n_in,
                              void* d_out, int out_size)
{
    const float* x    = (const float*)d_in[0];
    const float* y    = (const float*)d_in[1];
    const float* l1W1 = (const float*)d_in[2];
    const float* l1g  = (const float*)d_in[3];
    const float* l1b  = (const float*)d_in[4];
    const float* l1W2 = (const float*)d_in[5];
    const float* l1b2 = (const float*)d_in[6];
    const float* l2W1 = (const float*)d_in[7];
    const float* l2g  = (const float*)d_in[8];
    const float* l2b  = (const float*)d_in[9];
    const float* l2W2 = (const float*)d_in[10];
    const float* l2b2 = (const float*)d_in[11];
    const float* l3W1 = (const float*)d_in[12];
    const float* l3g  = (const float*)d_in[13];
    const float* l3b  = (const float*)d_in[14];
    const float* l3W2 = (const float*)d_in[15];
    const float* l3b2 = (const float*)d_in[16];
    float* out = (float*)d_out;

    int *rows2, *cnt2, *rows3, *cnt3, *t1, *t2, *t3;
    cudaGetSymbolAddress((void**)&rows2, g_rows2);
    cudaGetSymbolAddress((void**)&cnt2,  g_cnt2);
    cudaGetSymbolAddress((void**)&rows3, g_rows3);
    cudaGetSymbolAddress((void**)&cnt3,  g_cnt3);
    cudaGetSymbolAddress((void**)&t1,    g_tick1);
    cudaGetSymbolAddress((void**)&t2,    g_tick2);
    cudaGetSymbolAddress((void**)&t3,    g_tick3);

    constexpr int SM4 = smem_bytes(4);   // R=16 variants
    constexpr int SM2 = smem_bytes(2);   // R=8 variant

    cudaFuncSetAttribute((const void*)k_level<4, L1C, false, true>,
                         cudaFuncAttributeMaxDynamicSharedMemorySize, SM4);
    cudaFuncSetAttribute((const void*)k_level<4, L2C, true, false>,
                         cudaFuncAttributeMaxDynamicSharedMemorySize, SM4);
    cudaFuncSetAttribute((const void*)k_level<2, L3C, false, false>,
                         cudaFuncAttributeMaxDynamicSharedMemorySize, SM2);

    k_init<<<1, 256>>>();

    // level 1: dense, RT=4 (R=16), 8 row-slots x 32 segs = 256 blocks,
    // each block reuses its weight tile for 8 chunks
    k_level<4, L1C, false, true><<<dim3(8, FSEG, 1), 256, SM4>>>(
        x, nullptr, l1W1, l1g, l1b, l1W2, l1b2,
        nullptr, nullptr, out, cnt2, rows2, t1);

    // level 2: 16 experts, mixed features, RT=4 (R=16), 4 slots
    k_level<4, L2C, true, false><<<dim3(4, FSEG, L1C), 256, SM4>>>(
        x, y, l2W1, l2g, l2b, l2W2, l2b2,
        rows2, cnt2, out + (size_t)BB * L1C, cnt3, rows3, t2);

    // level 3: 128 experts, RT=2 (R=8), 2 slots
    k_level<2, L3C, false, false><<<dim3(2, FSEG, NE3), 256, SM2>>>(
        x, nullptr, l3W1, l3g, l3b, l3W2, l3b2,
        rows3, cnt3, out + (size_t)BB * (L1C + L2C), nullptr, nullptr, t3);
}

// round 15
// speedup vs baseline: 2.1102x; 2.1102x over previous
#include <cuda_runtime.h>
#include <cstdint>

// ---------------------------------------------------------------------------
// MultiLevelClassifier — routed experts, round 10.
//
// R9 failed: missing __syncthreads() between the cross-thread feature
// stores and the first GEMM read (mbar_wait orders only the TMA writes,
// not other threads' smem stores). This round = R9 + that barrier,
// restoring exactly the R7 barrier placement around the stage loop.
//
// Structure: FSEG=8 seg-blocks per (expert,chunk); weight stages 4 x 32KB
// double-buffered via cp.async.bulk (TMA/bulk engine, mbarrier expect_tx
// completion — the path rated at the full LTS cap on sm_103a); fused
// split-K finish (last-block-reduces, self-resetting tickets).
// ---------------------------------------------------------------------------

#define BB    1024
#define FF    1024
#define EE    256
#define L1C   16
#define L2C   8
#define L3C   32
#define NE3   128
#define FSEG  8
#define FS    (FF / FSEG)     // 128 features per seg-block
#define SROWS 32              // f-rows per bulk stage
#define SBYTES (SROWS * EE * 4)   // 32 KB
#define NST   (FS / SROWS)    // 4 stages per chunk

// scratch (device globals — no allocation allowed; zero-initialized)
__device__ int   g_cnt2[L1C];
__device__ int   g_cnt3[NE3];
__device__ int   g_rows2[L1C * BB];
__device__ int   g_rows3[NE3 * BB];
__device__ float g_part[FSEG * BB * EE];   // 8 MB split-K partials
__device__ int   g_tick1[64];
__device__ int   g_tick2[L1C * 64];
__device__ int   g_tick3[NE3 * 128];

// ---- packed f32x2 helpers --------------------------------------------------
__device__ __forceinline__ unsigned long long pack2f(float a, float b) {
    unsigned long long r;
    asm("mov.b64 %0, {%1, %2};" : "=l"(r) : "f"(a), "f"(b));
    return r;
}
__device__ __forceinline__ void fma_f32x2(unsigned long long& d,
                                          unsigned long long a,
                                          unsigned long long b) {
    asm("fma.rn.f32x2 %0, %1, %2, %0;" : "+l"(d) : "l"(a), "l"(b));
}
__device__ __forceinline__ float2 unpack2(unsigned long long v) {
    float2 r;
    asm("mov.b64 {%0, %1}, %2;" : "=f"(r.x), "=f"(r.y) : "l"(v));
    return r;
}

// ---- mbarrier + bulk-copy helpers -----------------------------------------
__device__ __forceinline__ uint32_t smem_u32(const void* p) {
    return (uint32_t)__cvta_generic_to_shared(p);
}
__device__ __forceinline__ void mbar_init(uint64_t* bar, uint32_t cnt) {
    asm volatile("mbarrier.init.shared.b64 [%0], %1;"
                 :: "r"(smem_u32(bar)), "r"(cnt) : "memory");
}
__device__ __forceinline__ void mbar_expect_tx(uint64_t* bar, uint32_t bytes) {
    asm volatile("mbarrier.arrive.expect_tx.shared.b64 _, [%0], %1;"
                 :: "r"(smem_u32(bar)), "r"(bytes) : "memory");
}
__device__ __forceinline__ void bulk_g2s(void* sdst, const void* gsrc,
                                         uint32_t bytes, uint64_t* bar) {
    asm volatile(
        "cp.async.bulk.shared::cta.global.mbarrier::complete_tx::bytes "
        "[%0], [%1], %2, [%3];"
        :: "r"(smem_u32(sdst)), "l"(gsrc), "r"(bytes), "r"(smem_u32(bar))
        : "memory");
}
__device__ __forceinline__ void mbar_wait(uint64_t* bar, uint32_t parity) {
    asm volatile(
        "{\n\t"
        ".reg .pred P1;\n\t"
        "WAIT_LOOP_%=:\n\t"
        "mbarrier.try_wait.parity.acquire.cta.shared::cta.b64 P1, [%0], %1, 0x989680;\n\t"
        "@P1 bra.uni WAIT_DONE_%=;\n\t"
        "bra.uni WAIT_LOOP_%=;\n\t"
        "WAIT_DONE_%=:\n\t"
        "}"
        :: "r"(smem_u32(bar)), "r"(parity) : "memory");
}

// ---------------------------------------------------------------------------
__global__ void k_init() {
    int t = threadIdx.x;
    if (t < L1C) g_cnt2[t] = 0;
    if (t < NE3) g_cnt3[t] = 0;
}

// ---------------------------------------------------------------------------
// Fused level kernel. Block (slot, seg(8), expert), 256 threads.
//   cg = tid&63 -> cols 4cg..4cg+3 ; rg = tid>>6 -> rows rg*RT.. (R=4*RT)
// ---------------------------------------------------------------------------
template <int RT, int L, bool MIX, bool DENSE>
__global__ __launch_bounds__(256) void k_level(
    const float* __restrict__ fx, const float* __restrict__ fy,
    const float* __restrict__ W1base,            // [NEXP][FF][EE]
    const float* __restrict__ gbase, const float* __restrict__ bbase,
    const float* __restrict__ W2base, const float* __restrict__ b2base,
    const int* __restrict__ rowlists, const int* __restrict__ cnts,
    float* __restrict__ logits_out,
    int* __restrict__ cnt_next, int* __restrict__ rows_next,
    int* __restrict__ ticks)
{
    constexpr int R    = 4 * RT;
    constexpr int CMAX = BB / R;
    const int tid  = threadIdx.x;
    const int cg   = tid & 63;
    const int rg   = tid >> 6;
    const int slot = blockIdx.x, nslot = gridDim.x;
    const int seg  = blockIdx.y;
    const int e    = blockIdx.z;
    const int f0   = seg * FS;
    const int cnt  = DENSE ? BB : cnts[e];

    const float* __restrict__ Wseg =
        W1base + (size_t)e * FF * EE + (size_t)f0 * EE;   // 128 KB slice
    const float* __restrict__ gg = gbase  + (size_t)e * EE;
    const float* __restrict__ bv = bbase  + (size_t)e * EE;
    const float* __restrict__ W2 = W2base + (size_t)e * EE * L;
    const float* __restrict__ b2 = b2base + (size_t)e * L;

    extern __shared__ char smraw[];
    float* wbuf0 = (float*)smraw;                    // 32 KB stage buffer
    float* wbuf1 = wbuf0 + SROWS * EE;               // 32 KB stage buffer
    float* feat  = wbuf1 + SROWS * EE;               // [R][FS]
    // finish scratch overlays the (drained) weight buffers
    float* act  = wbuf0;                             // [R][EE]
    float* reds = act  + R * EE;                     // [R][8]
    float* redq = reds + R * 8;                      // [R][8]
    float* mean = redq + R * 8;                      // [R]
    float* rstd = mean + R;                          // [R]
    float* lg   = rstd + R;                          // [R][32]
    __shared__ alignas(8) uint64_t s_mbar[2];
    __shared__ int sflag;

    if (slot * R >= cnt) return;                     // nothing for this slot

    if (tid == 0) { mbar_init(&s_mbar[0], 1); mbar_init(&s_mbar[1], 1); }
    __syncthreads();
    int ph0 = 0, ph1 = 0;
    float* wb[2] = { wbuf0, wbuf1 };

    for (int c = slot; c * R < cnt; c += nslot) {
        const int start = c * R;
        const int nr = min(R, cnt - start);
        const int* rowids = DENSE ? nullptr : (rowlists + e * BB + start);

        // ---- kick stage 0, then gather features (overlapped) ------------
        if (tid == 0) {
            mbar_expect_tx(&s_mbar[0], SBYTES);
            bulk_g2s(wb[0], Wseg, SBYTES, &s_mbar[0]);
        }
        for (int i = tid; i < R * FS / 4; i += 256) {
            int r  = i / (FS / 4);
            int j  = (i % (FS / 4)) * 4;
            int rr = (r < nr) ? r : 0;
            int b  = DENSE ? (start + rr) : rowids[rr];
            float4 v = *(const float4*)(fx + (size_t)b * FF + f0 + j);
            if (MIX) {
                float4 u = *(const float4*)(fy + (size_t)b * FF + f0 + j);
                v.x = 0.6f * v.x + 0.4f * u.x;
                v.y = 0.6f * v.y + 0.4f * u.y;
                v.z = 0.6f * v.z + 0.4f * u.z;
                v.w = 0.6f * v.w + 0.4f * u.w;
            }
            *(float4*)&feat[r * FS + j] = v;
        }
        __syncthreads();   // FIX: feat stores visible before any thread reads

        // ---- pipelined GEMM over 4 bulk stages --------------------------
        unsigned long long acc[RT][2];
        #pragma unroll
        for (int t = 0; t < RT; t++) { acc[t][0] = 0ull; acc[t][1] = 0ull; }

        #pragma unroll
        for (int s = 0; s < NST; s++) {
            const int bi = s & 1;
            if (s + 1 < NST && tid == 0) {     // prefetch next stage
                uint64_t* nb = &s_mbar[(s + 1) & 1];
                mbar_expect_tx(nb, SBYTES);
                bulk_g2s(wb[(s + 1) & 1],
                         Wseg + (size_t)(s + 1) * SROWS * EE, SBYTES, nb);
            }
            if (bi == 0) { mbar_wait(&s_mbar[0], ph0); ph0 ^= 1; }
            else         { mbar_wait(&s_mbar[1], ph1); ph1 ^= 1; }

            const float* wbp = wb[bi];
            const int fb = s * SROWS;
            #pragma unroll
            for (int f = 0; f < SROWS; f++) {
                ulonglong2 w = *(const ulonglong2*)&wbp[f * EE + 4 * cg];
                #pragma unroll
                for (int t = 0; t < RT; t++) {
                    float v = feat[(rg * RT + t) * FS + fb + f];
                    unsigned long long fv = pack2f(v, v);
                    fma_f32x2(acc[t][0], fv, w.x);
                    fma_f32x2(acc[t][1], fv, w.y);
                }
            }
            __syncthreads();   // buffer free before it is overwritten
        }

        // ---- write partials (STG.128) -----------------------------------
        #pragma unroll
        for (int t = 0; t < RT; t++) {
            int r = rg * RT + t;
            if (r < nr) {
                int b = DENSE ? (start + r) : rowids[r];
                float2 lo = unpack2(acc[t][0]);
                float2 hi = unpack2(acc[t][1]);
                *(float4*)&g_part[((size_t)seg * BB + b) * EE + 4 * cg] =
                    make_float4(lo.x, lo.y, hi.x, hi.y);
            }
        }

        // ---- split-K completion ticket ----------------------------------
        __threadfence();
        __syncthreads();
        if (tid == 0) {
            int* tk = &ticks[e * CMAX + c];
            int old = atomicAdd(tk, 1);
            if (old == FSEG - 1) *tk = 0;          // self-reset for replays
            sflag = old;
        }
        __syncthreads();
        if (sflag != FSEG - 1) continue;

        // =================== FINISH (reducer block only) =================
        __threadfence();

        float h[R];
        #pragma unroll
        for (int r = 0; r < R; r++) {
            int rr = (r < nr) ? r : 0;
            int b  = DENSE ? (start + rr) : rowids[rr];
            float s = 0.f;
            #pragma unroll
            for (int sg = 0; sg < FSEG; sg++)
                s += g_part[((size_t)sg * BB + b) * EE + tid];
            h[r] = s;
        }

        const int lane = tid & 31, wid = tid >> 5;
        #pragma unroll
        for (int r = 0; r < R; r++) {
            float s = h[r], q = h[r] * h[r];
            #pragma unroll
            for (int o = 16; o; o >>= 1) {
                s += __shfl_xor_sync(0xffffffffu, s, o);
                q += __shfl_xor_sync(0xffffffffu, q, o);
            }
            if (lane == 0) { reds[r * 8 + wid] = s; redq[r * 8 + wid] = q; }
        }
        __syncthreads();
        if (tid < R) {
            float s = 0.f, q = 0.f;
            #pragma unroll
            for (int w2i = 0; w2i < 8; w2i++) {
                s += reds[tid * 8 + w2i]; q += redq[tid * 8 + w2i];
            }
            float m   = s * (1.0f / EE);
            float var = q * (1.0f / EE) - m * m;
            mean[tid] = m;
            rstd[tid] = rsqrtf(var + 1e-5f);
        }
        __syncthreads();

        const float gt = gg[tid], bt = bv[tid];
        #pragma unroll
        for (int r = 0; r < R; r++) {
            float yv = (h[r] - mean[r]) * rstd[r] * gt + bt;
            act[r * EE + tid] = fmaxf(yv, 0.0f);
        }
        __syncthreads();

        // second matmul: logits
        for (int i = tid; i < nr * L; i += 256) {
            int r = i / L, col = i % L;
            float a = b2[col];
            const float* ar = &act[r * EE];
            #pragma unroll 8
            for (int k = 0; k < EE; k++) a += ar[k] * W2[k * L + col];
            lg[r * 32 + col] = a;
            int b = DENSE ? (start + r) : rowids[r];
            logits_out[(size_t)b * L + col] = a;
        }
        __syncthreads();

        // argmax + scatter
        if (cnt_next && tid < nr) {
            float best = lg[tid * 32];
            int   bi2  = 0;
            #pragma unroll
            for (int col = 1; col < L; col++) {
                float v = lg[tid * 32 + col];
                if (v > best) { best = v; bi2 = col; }
            }
            int b   = DENSE ? (start + tid) : rowids[tid];
            int nxt = e * L + bi2;
            int pos = atomicAdd(&cnt_next[nxt], 1);
            rows_next[nxt * BB + pos] = b;
        }
        __syncthreads();   // act/lg region reused as wbuf next chunk
    }
}

// dynamic smem: 2 stage buffers + feature tile
constexpr int smem_bytes_rt(int RT) {
    return 2 * SROWS * EE * 4 + 4 * RT * FS * 4;
}

// ---------------------------------------------------------------------------
extern "C" void kernel_launch(void* const* d_in, const int* in_sizes, int n_in,
                              void* d_out, int out_size)
{
    const float* x    = (const float*)d_in[0];
    const float* y    = (const float*)d_in[1];
    const float* l1W1 = (const float*)d_in[2];
    const float* l1g  = (const float*)d_in[3];
    const float* l1b  = (const float*)d_in[4];
    const float* l1W2 = (const float*)d_in[5];
    const float* l1b2 = (const float*)d_in[6];
    const float* l2W1 = (const float*)d_in[7];
    const float* l2g  = (const float*)d_in[8];
    const float* l2b  = (const float*)d_in[9];
    const float* l2W2 = (const float*)d_in[10];
    const float* l2b2 = (const float*)d_in[11];
    const float* l3W1 = (const float*)d_in[12];
    const float* l3g  = (const float*)d_in[13];
    const float* l3b  = (const float*)d_in[14];
    const float* l3W2 = (const float*)d_in[15];
    const float* l3b2 = (const float*)d_in[16];
    float* out = (float*)d_out;

    int *rows2, *cnt2, *rows3, *cnt3, *t1, *t2, *t3;
    cudaGetSymbolAddress((void**)&rows2, g_rows2);
    cudaGetSymbolAddress((void**)&cnt2,  g_cnt2);
    cudaGetSymbolAddress((void**)&rows3, g_rows3);
    cudaGetSymbolAddress((void**)&cnt3,  g_cnt3);
    cudaGetSymbolAddress((void**)&t1,    g_tick1);
    cudaGetSymbolAddress((void**)&t2,    g_tick2);
    cudaGetSymbolAddress((void**)&t3,    g_tick3);

    constexpr int SM4 = smem_bytes_rt(4);   // R=16 variants (~73.7 KB)
    constexpr int SM2 = smem_bytes_rt(2);   // R=8 variant  (~69.6 KB)

    cudaFuncSetAttribute((const void*)k_level<4, L1C, false, true>,
                         cudaFuncAttributeMaxDynamicSharedMemorySize, SM4);
    cudaFuncSetAttribute((const void*)k_level<4, L2C, true, false>,
                         cudaFuncAttributeMaxDynamicSharedMemorySize, SM4);
    cudaFuncSetAttribute((const void*)k_level<2, L3C, false, false>,
                         cudaFuncAttributeMaxDynamicSharedMemorySize, SM2);

    k_init<<<1, 256>>>();

    // level 1: dense, RT=4 (R=16), 64 chunks
    k_level<4, L1C, false, true><<<dim3(64, FSEG, 1), 256, SM4>>>(
        x, nullptr, l1W1, l1g, l1b, l1W2, l1b2,
        nullptr, nullptr, out, cnt2, rows2, t1);

    // level 2: 16 experts, mixed features, RT=4 (R=16)
    k_level<4, L2C, true, false><<<dim3(8, FSEG, L1C), 256, SM4>>>(
        x, y, l2W1, l2g, l2b, l2W2, l2b2,
        rows2, cnt2, out + (size_t)BB * L1C, cnt3, rows3, t2);

    // level 3: 128 experts, RT=2 (R=8)
    k_level<2, L3C, false, false><<<dim3(2, FSEG, NE3), 256, SM2>>>(
        x, nullptr, l3W1, l3g, l3b, l3W2, l3b2,
        rows3, cnt3, out + (size_t)BB * (L1C + L2C), nullptr, nullptr, t3);
}